// round 3
// baseline (speedup 1.0000x reference)
#include <cuda_runtime.h>
#include <math.h>

#define N_NODES 30000
#define N_EDGES 480000
#define BUCKET  64

// ---------------- scratch (static device globals; no allocation) ----------------
__device__ float g_bufA[N_NODES * 512];   // GEMM output h (per layer)
__device__ float g_bufB[N_NODES * 512];   // aggregated output (per layer)
__device__ float g_h3[N_NODES * 128];     // layer-3 h
__device__ float g_as[N_NODES * 4];
__device__ float g_ad[N_NODES * 4];
__device__ int   g_cnt[N_NODES];
__device__ int   g_csrc[N_NODES * BUCKET];
__device__ int   g_is64;

// ---------------- edge_index dtype probe ----------------
__global__ void k_detect(const void* __restrict__ ei) {
    if (threadIdx.x == 0) {
        const long long* p = (const long long*)ei;
        int ok = 1;
        for (int i = 0; i < 64; i++) {
            long long s = p[i];
            long long d = p[N_EDGES + i];
            if (s < 0 || s >= N_NODES || d < 0 || d >= N_NODES) { ok = 0; break; }
        }
        g_is64 = ok;
    }
}

__device__ __forceinline__ int edge_src(const void* ei, int i) {
    return g_is64 ? (int)((const long long*)ei)[i] : ((const int*)ei)[i];
}
__device__ __forceinline__ int edge_dst(const void* ei, int i) {
    return g_is64 ? (int)((const long long*)ei)[N_EDGES + i] : ((const int*)ei)[N_EDGES + i];
}

// ---------------- bucketed incoming-edge lists (no scan needed) ----------------
__global__ void k_initbuckets() {
    int i = blockIdx.x * blockDim.x + threadIdx.x;
    if (i < N_NODES) { g_cnt[i] = 1; g_csrc[i * BUCKET] = i; }  // self-loop
}

__global__ void k_scatter(const void* __restrict__ ei) {
    int i = blockIdx.x * blockDim.x + threadIdx.x;
    if (i < N_EDGES) {
        int s = edge_src(ei, i);
        int d = edge_dst(ei, i);
        int pos = atomicAdd(&g_cnt[d], 1);
        if (pos < BUCKET) g_csrc[d * BUCKET + pos] = s;
    }
}

// ---------------- packed f32x2 helpers ----------------
__device__ __forceinline__ void ffma2(unsigned long long& c, unsigned long long a,
                                      unsigned long long b) {
    asm("fma.rn.f32x2 %0, %1, %2, %0;" : "+l"(c) : "l"(a), "l"(b));
}
__device__ __forceinline__ float2 u2f2(unsigned long long v) {
    float2 r;
    asm("mov.b64 {%0, %1}, %2;" : "=f"(r.x), "=f"(r.y) : "l"(v));
    return r;
}

// ---------------- SGEMM 128x128x8, fp32 with packed FFMA2 ----------------
// A: MxK row-major, B: KxN row-major, C: MxN row-major. N%128==0, K%8==0.
// A tile stored DUPLICATED in shared: As2[k][2r]=As2[k][2r+1]=A[r][k], so a
// single LDS.128 yields two broadcast-ready f32x2 pairs with no MOV packing.
__global__ __launch_bounds__(256, 2) void k_sgemm(
    const float* __restrict__ A, const float* __restrict__ B, float* __restrict__ C,
    int M, int N, int K)
{
    __shared__ float As2[8][264];   // duplicated A, padded
    __shared__ float Bs[8][132];

    int tid = threadIdx.x;
    int trow = (tid >> 4) * 8;
    int tcol = (tid & 15) * 8;

    int arow = tid >> 1;              // 0..127
    int acol = (tid & 1) * 4;         // 0 or 4
    int brow = tid >> 5;              // 0..7
    int bcol = (tid & 31) * 4;        // 0..124

    int gArow = blockIdx.y * 128 + arow;
    bool aval = gArow < M;
    const float* Aptr = A + (size_t)(aval ? gArow : 0) * K + acol;
    const float* Bptr = B + (size_t)brow * N + blockIdx.x * 128 + bcol;

    unsigned long long acc[8][4];
    #pragma unroll
    for (int i = 0; i < 8; i++)
        #pragma unroll
        for (int j = 0; j < 4; j++) acc[i][j] = 0ull;

    float4 a4 = aval ? *(const float4*)Aptr : make_float4(0.f, 0.f, 0.f, 0.f);
    float4 b4 = *(const float4*)Bptr;

    for (int k0 = 0; k0 < K; k0 += 8) {
        // stage current tile to shared (A duplicated)
        *(float2*)&As2[acol + 0][2 * arow] = make_float2(a4.x, a4.x);
        *(float2*)&As2[acol + 1][2 * arow] = make_float2(a4.y, a4.y);
        *(float2*)&As2[acol + 2][2 * arow] = make_float2(a4.z, a4.z);
        *(float2*)&As2[acol + 3][2 * arow] = make_float2(a4.w, a4.w);
        *(float4*)&Bs[brow][bcol] = b4;
        __syncthreads();

        // prefetch next tile into registers (latency overlaps FMA block)
        if (k0 + 8 < K) {
            Aptr += 8;
            Bptr += (size_t)8 * N;
            a4 = aval ? *(const float4*)Aptr : make_float4(0.f, 0.f, 0.f, 0.f);
            b4 = *(const float4*)Bptr;
        }

        #pragma unroll
        for (int kk = 0; kk < 8; kk++) {
            unsigned long long ad[8], bd[4];
            // 8 duplicated A pairs: 4x LDS.128
            *(ulonglong2*)(ad + 0) = *(const ulonglong2*)&As2[kk][2 * trow + 0];
            *(ulonglong2*)(ad + 2) = *(const ulonglong2*)&As2[kk][2 * trow + 4];
            *(ulonglong2*)(ad + 4) = *(const ulonglong2*)&As2[kk][2 * trow + 8];
            *(ulonglong2*)(ad + 6) = *(const ulonglong2*)&As2[kk][2 * trow + 12];
            // 4 B pairs (contiguous columns): 2x LDS.128
            *(ulonglong2*)(bd + 0) = *(const ulonglong2*)&Bs[kk][tcol + 0];
            *(ulonglong2*)(bd + 2) = *(const ulonglong2*)&Bs[kk][tcol + 4];
            #pragma unroll
            for (int i = 0; i < 8; i++)
                #pragma unroll
                for (int j = 0; j < 4; j++)
                    ffma2(acc[i][j], ad[i], bd[j]);
        }
        __syncthreads();
    }

    int crow0 = blockIdx.y * 128 + trow;
    int ccol0 = blockIdx.x * 128 + tcol;
    #pragma unroll
    for (int i = 0; i < 8; i++) {
        int r = crow0 + i;
        if (r < M) {
            float2 c0 = u2f2(acc[i][0]), c1 = u2f2(acc[i][1]);
            float2 c2 = u2f2(acc[i][2]), c3 = u2f2(acc[i][3]);
            float* cp = C + (size_t)r * N + ccol0;
            *(float4*)(cp)     = make_float4(c0.x, c0.y, c1.x, c1.y);
            *(float4*)(cp + 4) = make_float4(c2.x, c2.y, c3.x, c3.y);
        }
    }
}

// ---------------- attention projections ----------------
__global__ void k_proj4(const float* __restrict__ h, const float* __restrict__ att_s,
                        const float* __restrict__ att_d)
{
    int n = blockIdx.x;
    int w = threadIdx.x >> 5, lane = threadIdx.x & 31;
    int c = w * 128 + lane * 4;
    float4 hv = *(const float4*)(h + (size_t)n * 512 + c);
    float4 sv = *(const float4*)(att_s + c);
    float4 dv = *(const float4*)(att_d + c);
    float ss = hv.x * sv.x + hv.y * sv.y + hv.z * sv.z + hv.w * sv.w;
    float dd = hv.x * dv.x + hv.y * dv.y + hv.z * dv.z + hv.w * dv.w;
    #pragma unroll
    for (int d = 16; d; d >>= 1) {
        ss += __shfl_xor_sync(0xffffffffu, ss, d);
        dd += __shfl_xor_sync(0xffffffffu, dd, d);
    }
    if (lane == 0) { g_as[n * 4 + w] = ss; g_ad[n * 4 + w] = dd; }
}

__global__ void k_proj1(const float* __restrict__ h, const float* __restrict__ att_s,
                        const float* __restrict__ att_d)
{
    int node = blockIdx.x * 8 + (threadIdx.x >> 5);
    if (node >= N_NODES) return;
    int lane = threadIdx.x & 31;
    int c = lane * 4;
    float4 hv = *(const float4*)(h + (size_t)node * 128 + c);
    float4 sv = *(const float4*)(att_s + c);
    float4 dv = *(const float4*)(att_d + c);
    float ss = hv.x * sv.x + hv.y * sv.y + hv.z * sv.z + hv.w * sv.w;
    float dd = hv.x * dv.x + hv.y * dv.y + hv.z * dv.z + hv.w * dv.w;
    #pragma unroll
    for (int d = 16; d; d >>= 1) {
        ss += __shfl_xor_sync(0xffffffffu, ss, d);
        dd += __shfl_xor_sync(0xffffffffu, dd, d);
    }
    if (lane == 0) { g_as[node] = ss; g_ad[node] = dd; }
}

__device__ __forceinline__ float lrelu(float a) { return a > 0.f ? a : 0.2f * a; }

// ---------------- fused softmax + aggregation ----------------
template<bool RELU>
__global__ void k_agg4(const float* __restrict__ h, const float* __restrict__ bias,
                       float* __restrict__ out)
{
    int n = blockIdx.x;
    int w = threadIdx.x >> 5, lane = threadIdx.x & 31;
    int beg = n * BUCKET;
    int cnt = min(g_cnt[n], BUCKET);
    int end = beg + cnt;
    float adst = g_ad[n * 4 + w];

    float mx = -1e30f;
    for (int i = beg + lane; i < end; i += 32)
        mx = fmaxf(mx, g_as[g_csrc[i] * 4 + w]);
    #pragma unroll
    for (int d = 16; d; d >>= 1)
        mx = fmaxf(mx, __shfl_xor_sync(0xffffffffu, mx, d));
    float m = lrelu(mx + adst);

    float4 acc = make_float4(0.f, 0.f, 0.f, 0.f);
    float denom = 0.f;
    int c0 = w * 128 + lane * 4;
    #pragma unroll 2
    for (int i = beg; i < end; i++) {
        int s = g_csrc[i];
        float a = lrelu(g_as[s * 4 + w] + adst);
        float ex = __expf(a - m);
        denom += ex;
        float4 hv = *(const float4*)(h + (size_t)s * 512 + c0);
        acc.x = fmaf(ex, hv.x, acc.x);
        acc.y = fmaf(ex, hv.y, acc.y);
        acc.z = fmaf(ex, hv.z, acc.z);
        acc.w = fmaf(ex, hv.w, acc.w);
    }
    float inv = 1.f / denom;
    float4 b = *(const float4*)(bias + c0);
    float4 o;
    o.x = acc.x * inv + b.x;
    o.y = acc.y * inv + b.y;
    o.z = acc.z * inv + b.z;
    o.w = acc.w * inv + b.w;
    if (RELU) {
        o.x = fmaxf(o.x, 0.f); o.y = fmaxf(o.y, 0.f);
        o.z = fmaxf(o.z, 0.f); o.w = fmaxf(o.w, 0.f);
    }
    *(float4*)(out + (size_t)n * 512 + c0) = o;
}

__global__ void k_agg1(const float* __restrict__ h, const float* __restrict__ bias,
                       float* __restrict__ out)
{
    int node = blockIdx.x * 8 + (threadIdx.x >> 5);
    if (node >= N_NODES) return;
    int lane = threadIdx.x & 31;
    int beg = node * BUCKET;
    int cnt = min(g_cnt[node], BUCKET);
    int end = beg + cnt;
    float adst = g_ad[node];

    float mx = -1e30f;
    for (int i = beg + lane; i < end; i += 32)
        mx = fmaxf(mx, g_as[g_csrc[i]]);
    #pragma unroll
    for (int d = 16; d; d >>= 1)
        mx = fmaxf(mx, __shfl_xor_sync(0xffffffffu, mx, d));
    float m = lrelu(mx + adst);

    float4 acc = make_float4(0.f, 0.f, 0.f, 0.f);
    float denom = 0.f;
    int c0 = lane * 4;
    #pragma unroll 2
    for (int i = beg; i < end; i++) {
        int s = g_csrc[i];
        float a = lrelu(g_as[s] + adst);
        float ex = __expf(a - m);
        denom += ex;
        float4 hv = *(const float4*)(h + (size_t)s * 128 + c0);
        acc.x = fmaf(ex, hv.x, acc.x);
        acc.y = fmaf(ex, hv.y, acc.y);
        acc.z = fmaf(ex, hv.z, acc.z);
        acc.w = fmaf(ex, hv.w, acc.w);
    }
    float inv = 1.f / denom;
    float4 b = *(const float4*)(bias + c0);
    float4 o;
    o.x = acc.x * inv + b.x;
    o.y = acc.y * inv + b.y;
    o.z = acc.z * inv + b.z;
    o.w = acc.w * inv + b.w;
    *(float4*)(out + (size_t)node * 128 + c0) = o;
}

// ---------------- launch ----------------
extern "C" void kernel_launch(void* const* d_in, const int* in_sizes, int n_in,
                              void* d_out, int out_size)
{
    const float* x    = (const float*)d_in[0];
    const void*  ei   = d_in[1];
    const float* W1   = (const float*)d_in[2];
    const float* as1  = (const float*)d_in[3];
    const float* ad1  = (const float*)d_in[4];
    const float* b1   = (const float*)d_in[5];
    const float* W2   = (const float*)d_in[6];
    const float* as2  = (const float*)d_in[7];
    const float* ad2  = (const float*)d_in[8];
    const float* b2   = (const float*)d_in[9];
    const float* W3   = (const float*)d_in[10];
    const float* as3  = (const float*)d_in[11];
    const float* ad3  = (const float*)d_in[12];
    const float* b3   = (const float*)d_in[13];
    float*       out  = (float*)d_out;

    float *bufA, *bufB, *h3;
    cudaGetSymbolAddress((void**)&bufA, g_bufA);
    cudaGetSymbolAddress((void**)&bufB, g_bufB);
    cudaGetSymbolAddress((void**)&h3,   g_h3);

    // edge_index dtype probe + bucketed incoming lists (self-loops included)
    k_detect<<<1, 32>>>(ei);
    k_initbuckets<<<(N_NODES + 255) / 256, 256>>>();
    k_scatter<<<(N_EDGES + 255) / 256, 256>>>(ei);

    dim3 g1(512 / 128, (N_NODES + 127) / 128);
    dim3 g3(128 / 128, (N_NODES + 127) / 128);

    // layer 1
    k_sgemm<<<g1, 256>>>(x, W1, bufA, N_NODES, 512, 256);
    k_proj4<<<N_NODES, 128>>>(bufA, as1, ad1);
    k_agg4<true><<<N_NODES, 128>>>(bufA, b1, bufB);

    // layer 2
    k_sgemm<<<g1, 256>>>(bufB, W2, bufA, N_NODES, 512, 512);
    k_proj4<<<N_NODES, 128>>>(bufA, as2, ad2);
    k_agg4<true><<<N_NODES, 128>>>(bufA, b2, bufB);

    // layer 3
    k_sgemm<<<g3, 256>>>(bufB, W3, h3, N_NODES, 128, 512);
    k_proj1<<<(N_NODES + 7) / 8, 256>>>(h3, as3, ad3);
    k_agg1<<<(N_NODES + 7) / 8, 256>>>(h3, b3, out);
}

// round 6
// speedup vs baseline: 1.6446x; 1.6446x over previous
#include <cuda_runtime.h>
#include <cuda_bf16.h>
#include <math.h>
#include <stdint.h>

#define N_NODES 30000
#define N_EDGES 480000
#define BUCKET  64

// ---------------- scratch (static device globals; no allocation) ----------------
__device__ float g_bufA[N_NODES * 512];            // GEMM output h (per layer)
__device__ float g_h3[N_NODES * 128];              // layer-3 GEMM output
__device__ __nv_bfloat16 g_ahi[N_NODES * 512];     // GEMM A operand hi
__device__ __nv_bfloat16 g_alo[N_NODES * 512];     // GEMM A operand lo
__device__ __nv_bfloat16 g_w1hi[512 * 256], g_w1lo[512 * 256];   // [N,K]
__device__ __nv_bfloat16 g_w2hi[512 * 512], g_w2lo[512 * 512];
__device__ __nv_bfloat16 g_w3hi[128 * 512], g_w3lo[128 * 512];
__device__ float g_as[N_NODES * 4];
__device__ float g_ad[N_NODES * 4];
__device__ int   g_cnt[N_NODES];
__device__ int   g_csrc[N_NODES * BUCKET];
__device__ int   g_is64;

// ---------------- PTX helpers (base ISA only: ldmatrix + mma.sync) ----------------
__device__ __forceinline__ uint32_t smem_u32(const void* p) {
    uint32_t a;
    asm("{ .reg .u64 t; cvta.to.shared.u64 t, %1; cvt.u32.u64 %0, t; }" : "=r"(a) : "l"(p));
    return a;
}
__device__ __forceinline__ void ldsm4(uint32_t* r, uint32_t addr) {
    asm volatile("ldmatrix.sync.aligned.m8n8.x4.shared.b16 {%0,%1,%2,%3}, [%4];"
                 : "=r"(r[0]), "=r"(r[1]), "=r"(r[2]), "=r"(r[3]) : "r"(addr));
}
__device__ __forceinline__ void mma16816(float* c, const uint32_t* a, const uint32_t* b) {
    asm volatile(
        "mma.sync.aligned.m16n8k16.row.col.f32.bf16.bf16.f32 "
        "{%0,%1,%2,%3}, {%4,%5,%6,%7}, {%8,%9}, {%0,%1,%2,%3};"
        : "+f"(c[0]), "+f"(c[1]), "+f"(c[2]), "+f"(c[3])
        : "r"(a[0]), "r"(a[1]), "r"(a[2]), "r"(a[3]), "r"(b[0]), "r"(b[1]));
}

// ---------------- edge_index dtype probe ----------------
__global__ void k_detect(const void* __restrict__ ei) {
    if (threadIdx.x == 0) {
        const long long* p = (const long long*)ei;
        int ok = 1;
        for (int i = 0; i < 64; i++) {
            long long s = p[i];
            long long d = p[N_EDGES + i];
            if (s < 0 || s >= N_NODES || d < 0 || d >= N_NODES) { ok = 0; break; }
        }
        g_is64 = ok;
    }
}
__device__ __forceinline__ int edge_src(const void* ei, int i) {
    return g_is64 ? (int)((const long long*)ei)[i] : ((const int*)ei)[i];
}
__device__ __forceinline__ int edge_dst(const void* ei, int i) {
    return g_is64 ? (int)((const long long*)ei)[N_EDGES + i] : ((const int*)ei)[N_EDGES + i];
}

// ---------------- bucketed incoming-edge lists ----------------
__global__ void k_initbuckets() {
    int i = blockIdx.x * blockDim.x + threadIdx.x;
    if (i < N_NODES) { g_cnt[i] = 1; g_csrc[i * BUCKET] = i; }
}
__global__ void k_scatter(const void* __restrict__ ei) {
    int i = blockIdx.x * blockDim.x + threadIdx.x;
    if (i < N_EDGES) {
        int s = edge_src(ei, i);
        int d = edge_dst(ei, i);
        int pos = atomicAdd(&g_cnt[d], 1);
        if (pos < BUCKET) g_csrc[d * BUCKET + pos] = s;
    }
}

// ---------------- float -> bf16 hi/lo splits ----------------
__device__ __forceinline__ void split1(float v, __nv_bfloat16& hi, __nv_bfloat16& lo) {
    hi = __float2bfloat16_rn(v);
    lo = __float2bfloat16_rn(v - __bfloat162float(hi));
}

__global__ void k_splitA(const float* __restrict__ src, __nv_bfloat16* __restrict__ hi,
                         __nv_bfloat16* __restrict__ lo, int n4) {
    int i = blockIdx.x * blockDim.x + threadIdx.x;
    if (i < n4) {
        float4 v = ((const float4*)src)[i];
        __nv_bfloat16 h0, h1, h2, h3, l0, l1, l2, l3;
        split1(v.x, h0, l0); split1(v.y, h1, l1);
        split1(v.z, h2, l2); split1(v.w, h3, l3);
        ((__nv_bfloat162*)hi)[2 * i]     = __nv_bfloat162(h0, h1);
        ((__nv_bfloat162*)hi)[2 * i + 1] = __nv_bfloat162(h2, h3);
        ((__nv_bfloat162*)lo)[2 * i]     = __nv_bfloat162(l0, l1);
        ((__nv_bfloat162*)lo)[2 * i + 1] = __nv_bfloat162(l2, l3);
    }
}

// W [K,N] fp32 -> hi/lo [N,K] bf16 (transpose + split)
__global__ void k_splitW(const float* __restrict__ W, __nv_bfloat16* __restrict__ hi,
                         __nv_bfloat16* __restrict__ lo, int K, int N) {
    int i = blockIdx.x * blockDim.x + threadIdx.x;
    if (i < K * N) {
        int k = i / N, n = i % N;
        __nv_bfloat16 h, l;
        split1(W[i], h, l);
        hi[(size_t)n * K + k] = h;
        lo[(size_t)n * K + k] = l;
    }
}

// ---------------- mma.sync split-bf16 GEMM ----------------
// C[M,N] fp32 row-major = A[M,K] @ W[K,N]; A*,B* bf16 hi/lo, A in [M,K], B in [N,K].
// CTA 128x128 tile, 256 thr (8 warps 4x2, each 32x64), K chunked by 32.
// smem tiles padded to stride 40 bf16 (80B) for conflict-free ldmatrix.
#define TPAD 40
#define TBYTES (128 * TPAD * 2)   // 10240 per tile

__global__ __launch_bounds__(256) void k_mma_gemm(
    const __nv_bfloat16* __restrict__ Ahi, const __nv_bfloat16* __restrict__ Alo,
    const __nv_bfloat16* __restrict__ Bhi, const __nv_bfloat16* __restrict__ Blo,
    float* __restrict__ C, int M, int N, int K)
{
    __shared__ char smem[4 * TBYTES];
    const uint32_t sAhi = smem_u32(smem);
    const uint32_t sAlo = sAhi + TBYTES;
    const uint32_t sBhi = sAhi + 2 * TBYTES;
    const uint32_t sBlo = sAhi + 3 * TBYTES;

    int tid = threadIdx.x;
    int lane = tid & 31, wid = tid >> 5;
    int mw = wid & 3, nw = wid >> 2;
    int m0 = blockIdx.y * 128, n0 = blockIdx.x * 128;

    // staging: thread handles rows {tid>>2, tid>>2 + 64}, 16B chunk cq = tid&3
    int row0 = tid >> 2, cq = tid & 3;
    const uint4* pA[2][2];   // [hi/lo][j]
    const uint4* pB[2][2];
    bool aok[2];
    uint32_t dstoff[2];
    #pragma unroll
    for (int j = 0; j < 2; j++) {
        int rr = row0 + j * 64;
        int ar = m0 + rr;
        aok[j] = ar < M;
        pA[0][j] = (const uint4*)(Ahi + (size_t)(aok[j] ? ar : 0) * K) + cq;
        pA[1][j] = (const uint4*)(Alo + (size_t)(aok[j] ? ar : 0) * K) + cq;
        pB[0][j] = (const uint4*)(Bhi + (size_t)(n0 + rr) * K) + cq;
        pB[1][j] = (const uint4*)(Blo + (size_t)(n0 + rr) * K) + cq;
        dstoff[j] = (uint32_t)(rr * TPAD + cq * 8) * 2;
    }

    // ldmatrix source offsets
    int arow = mw * 32 + (lane & 15);
    uint32_t aoff = (uint32_t)(arow * TPAD + ((lane >> 4) << 3)) * 2;
    int brow = nw * 64 + (lane & 7) + ((lane >> 4) << 3);
    uint32_t boff = (uint32_t)(brow * TPAD + (((lane >> 3) & 1) << 3)) * 2;

    float acc[2][8][4];
    #pragma unroll
    for (int i = 0; i < 2; i++)
        #pragma unroll
        for (int j = 0; j < 8; j++)
            #pragma unroll
            for (int q = 0; q < 4; q++) acc[i][j][q] = 0.f;

    const uint4 z4 = make_uint4(0, 0, 0, 0);
    int nchunk = K >> 5;
    for (int c = 0; c < nchunk; c++) {
        __syncthreads();
        int kq = c * 4;
        #pragma unroll
        for (int j = 0; j < 2; j++) {
            *(uint4*)(smem + (dstoff[j]))               = aok[j] ? pA[0][j][kq] : z4;
            *(uint4*)(smem + (dstoff[j] + TBYTES))      = aok[j] ? pA[1][j][kq] : z4;
            *(uint4*)(smem + (dstoff[j] + 2 * TBYTES))  = pB[0][j][kq];
            *(uint4*)(smem + (dstoff[j] + 3 * TBYTES))  = pB[1][j][kq];
        }
        __syncthreads();

        #pragma unroll
        for (int k16 = 0; k16 < 2; k16++) {
            uint32_t kb = k16 * 32;   // 16 bf16 = 32B
            uint32_t ahi[2][4], alo[2][4];
            #pragma unroll
            for (int mt = 0; mt < 2; mt++) {
                ldsm4(ahi[mt], sAhi + aoff + mt * (16 * TPAD * 2) + kb);
                ldsm4(alo[mt], sAlo + aoff + mt * (16 * TPAD * 2) + kb);
            }
            uint32_t bhi[8][2], blo[8][2];
            #pragma unroll
            for (int np = 0; np < 4; np++) {
                uint32_t r[4];
                ldsm4(r, sBhi + boff + np * (16 * TPAD * 2) + kb);
                bhi[2 * np][0] = r[0]; bhi[2 * np][1] = r[1];
                bhi[2 * np + 1][0] = r[2]; bhi[2 * np + 1][1] = r[3];
                ldsm4(r, sBlo + boff + np * (16 * TPAD * 2) + kb);
                blo[2 * np][0] = r[0]; blo[2 * np][1] = r[1];
                blo[2 * np + 1][0] = r[2]; blo[2 * np + 1][1] = r[3];
            }
            #pragma unroll
            for (int mt = 0; mt < 2; mt++)
                #pragma unroll
                for (int nt = 0; nt < 8; nt++) {
                    mma16816(acc[mt][nt], ahi[mt], bhi[nt]);
                    mma16816(acc[mt][nt], ahi[mt], blo[nt]);
                    mma16816(acc[mt][nt], alo[mt], bhi[nt]);
                }
        }
    }

    // epilogue
    int rbase = m0 + mw * 32 + (lane >> 2);
    int cbase = n0 + nw * 64 + (lane & 3) * 2;
    #pragma unroll
    for (int mt = 0; mt < 2; mt++) {
        int r = rbase + mt * 16;
        #pragma unroll
        for (int nt = 0; nt < 8; nt++) {
            int col = cbase + nt * 8;
            if (r < M)
                *(float2*)(C + (size_t)r * N + col) = make_float2(acc[mt][nt][0], acc[mt][nt][1]);
            if (r + 8 < M)
                *(float2*)(C + (size_t)(r + 8) * N + col) = make_float2(acc[mt][nt][2], acc[mt][nt][3]);
        }
    }
}

// ---------------- attention projections ----------------
__global__ void k_proj4(const float* __restrict__ h, const float* __restrict__ att_s,
                        const float* __restrict__ att_d)
{
    int n = blockIdx.x;
    int w = threadIdx.x >> 5, lane = threadIdx.x & 31;
    int c = w * 128 + lane * 4;
    float4 hv = *(const float4*)(h + (size_t)n * 512 + c);
    float4 sv = *(const float4*)(att_s + c);
    float4 dv = *(const float4*)(att_d + c);
    float ss = hv.x * sv.x + hv.y * sv.y + hv.z * sv.z + hv.w * sv.w;
    float dd = hv.x * dv.x + hv.y * dv.y + hv.z * dv.z + hv.w * dv.w;
    #pragma unroll
    for (int d = 16; d; d >>= 1) {
        ss += __shfl_xor_sync(0xffffffffu, ss, d);
        dd += __shfl_xor_sync(0xffffffffu, dd, d);
    }
    if (lane == 0) { g_as[n * 4 + w] = ss; g_ad[n * 4 + w] = dd; }
}

__global__ void k_proj1(const float* __restrict__ h, const float* __restrict__ att_s,
                        const float* __restrict__ att_d)
{
    int node = blockIdx.x * 8 + (threadIdx.x >> 5);
    if (node >= N_NODES) return;
    int lane = threadIdx.x & 31;
    int c = lane * 4;
    float4 hv = *(const float4*)(h + (size_t)node * 128 + c);
    float4 sv = *(const float4*)(att_s + c);
    float4 dv = *(const float4*)(att_d + c);
    float ss = hv.x * sv.x + hv.y * sv.y + hv.z * sv.z + hv.w * sv.w;
    float dd = hv.x * dv.x + hv.y * dv.y + hv.z * dv.z + hv.w * dv.w;
    #pragma unroll
    for (int d = 16; d; d >>= 1) {
        ss += __shfl_xor_sync(0xffffffffu, ss, d);
        dd += __shfl_xor_sync(0xffffffffu, dd, d);
    }
    if (lane == 0) { g_as[node] = ss; g_ad[node] = dd; }
}

__device__ __forceinline__ float lrelu(float a) { return a > 0.f ? a : 0.2f * a; }

// ---------------- fused softmax + aggregation -> bf16 hi/lo for next GEMM ----------------
__global__ void k_agg4(const float* __restrict__ h, const float* __restrict__ bias,
                       __nv_bfloat16* __restrict__ ohi, __nv_bfloat16* __restrict__ olo)
{
    int n = blockIdx.x;
    int w = threadIdx.x >> 5, lane = threadIdx.x & 31;
    int beg = n * BUCKET;
    int cnt = min(g_cnt[n], BUCKET);
    int end = beg + cnt;
    float adst = g_ad[n * 4 + w];

    float mx = -1e30f;
    for (int i = beg + lane; i < end; i += 32)
        mx = fmaxf(mx, g_as[g_csrc[i] * 4 + w]);
    #pragma unroll
    for (int d = 16; d; d >>= 1)
        mx = fmaxf(mx, __shfl_xor_sync(0xffffffffu, mx, d));
    float m = lrelu(mx + adst);

    float4 acc = make_float4(0.f, 0.f, 0.f, 0.f);
    float denom = 0.f;
    int c0 = w * 128 + lane * 4;
    #pragma unroll 2
    for (int i = beg; i < end; i++) {
        int s = g_csrc[i];
        float a = lrelu(g_as[s * 4 + w] + adst);
        float ex = __expf(a - m);
        denom += ex;
        float4 hv = *(const float4*)(h + (size_t)s * 512 + c0);
        acc.x = fmaf(ex, hv.x, acc.x);
        acc.y = fmaf(ex, hv.y, acc.y);
        acc.z = fmaf(ex, hv.z, acc.z);
        acc.w = fmaf(ex, hv.w, acc.w);
    }
    float inv = 1.f / denom;
    float4 b = *(const float4*)(bias + c0);
    float o0 = fmaxf(acc.x * inv + b.x, 0.f);
    float o1 = fmaxf(acc.y * inv + b.y, 0.f);
    float o2 = fmaxf(acc.z * inv + b.z, 0.f);
    float o3 = fmaxf(acc.w * inv + b.w, 0.f);
    __nv_bfloat16 h0, h1, h2, h3, l0, l1, l2, l3;
    split1(o0, h0, l0); split1(o1, h1, l1); split1(o2, h2, l2); split1(o3, h3, l3);
    size_t idx = (size_t)n * 512 + c0;
    *(__nv_bfloat162*)(ohi + idx)     = __nv_bfloat162(h0, h1);
    *(__nv_bfloat162*)(ohi + idx + 2) = __nv_bfloat162(h2, h3);
    *(__nv_bfloat162*)(olo + idx)     = __nv_bfloat162(l0, l1);
    *(__nv_bfloat162*)(olo + idx + 2) = __nv_bfloat162(l2, l3);
}

__global__ void k_agg1(const float* __restrict__ h, const float* __restrict__ bias,
                       float* __restrict__ out)
{
    int node = blockIdx.x * 8 + (threadIdx.x >> 5);
    if (node >= N_NODES) return;
    int lane = threadIdx.x & 31;
    int beg = node * BUCKET;
    int cnt = min(g_cnt[node], BUCKET);
    int end = beg + cnt;
    float adst = g_ad[node];

    float mx = -1e30f;
    for (int i = beg + lane; i < end; i += 32)
        mx = fmaxf(mx, g_as[g_csrc[i]]);
    #pragma unroll
    for (int d = 16; d; d >>= 1)
        mx = fmaxf(mx, __shfl_xor_sync(0xffffffffu, mx, d));
    float m = lrelu(mx + adst);

    float4 acc = make_float4(0.f, 0.f, 0.f, 0.f);
    float denom = 0.f;
    int c0 = lane * 4;
    #pragma unroll 2
    for (int i = beg; i < end; i++) {
        int s = g_csrc[i];
        float a = lrelu(g_as[s] + adst);
        float ex = __expf(a - m);
        denom += ex;
        float4 hv = *(const float4*)(h + (size_t)s * 128 + c0);
        acc.x = fmaf(ex, hv.x, acc.x);
        acc.y = fmaf(ex, hv.y, acc.y);
        acc.z = fmaf(ex, hv.z, acc.z);
        acc.w = fmaf(ex, hv.w, acc.w);
    }
    float inv = 1.f / denom;
    float4 b = *(const float4*)(bias + c0);
    float4 o;
    o.x = acc.x * inv + b.x;
    o.y = acc.y * inv + b.y;
    o.z = acc.z * inv + b.z;
    o.w = acc.w * inv + b.w;
    *(float4*)(out + (size_t)node * 128 + c0) = o;
}

// ---------------- launch ----------------
extern "C" void kernel_launch(void* const* d_in, const int* in_sizes, int n_in,
                              void* d_out, int out_size)
{
    const float* x    = (const float*)d_in[0];
    const void*  ei   = d_in[1];
    const float* W1   = (const float*)d_in[2];
    const float* as1  = (const float*)d_in[3];
    const float* ad1  = (const float*)d_in[4];
    const float* b1   = (const float*)d_in[5];
    const float* W2   = (const float*)d_in[6];
    const float* as2  = (const float*)d_in[7];
    const float* ad2  = (const float*)d_in[8];
    const float* b2   = (const float*)d_in[9];
    const float* W3   = (const float*)d_in[10];
    const float* as3  = (const float*)d_in[11];
    const float* ad3  = (const float*)d_in[12];
    const float* b3   = (const float*)d_in[13];
    float*       out  = (float*)d_out;

    float *bufA, *h3;
    __nv_bfloat16 *ahi, *alo, *w1hi, *w1lo, *w2hi, *w2lo, *w3hi, *w3lo;
    cudaGetSymbolAddress((void**)&bufA, g_bufA);
    cudaGetSymbolAddress((void**)&h3,   g_h3);
    cudaGetSymbolAddress((void**)&ahi,  g_ahi);
    cudaGetSymbolAddress((void**)&alo,  g_alo);
    cudaGetSymbolAddress((void**)&w1hi, g_w1hi);
    cudaGetSymbolAddress((void**)&w1lo, g_w1lo);
    cudaGetSymbolAddress((void**)&w2hi, g_w2hi);
    cudaGetSymbolAddress((void**)&w2lo, g_w2lo);
    cudaGetSymbolAddress((void**)&w3hi, g_w3hi);
    cudaGetSymbolAddress((void**)&w3lo, g_w3lo);

    // graph build + operand prep
    k_detect<<<1, 32>>>(ei);
    k_initbuckets<<<(N_NODES + 255) / 256, 256>>>();
    k_scatter<<<(N_EDGES + 255) / 256, 256>>>(ei);
    k_splitW<<<(256 * 512 + 255) / 256, 256>>>(W1, w1hi, w1lo, 256, 512);
    k_splitW<<<(512 * 512 + 255) / 256, 256>>>(W2, w2hi, w2lo, 512, 512);
    k_splitW<<<(512 * 128 + 255) / 256, 256>>>(W3, w3hi, w3lo, 512, 128);
    k_splitA<<<(N_NODES * 256 / 4 + 255) / 256, 256>>>(x, ahi, alo, N_NODES * 256 / 4);

    dim3 gt1(512 / 128, (N_NODES + 127) / 128);
    dim3 gt3(128 / 128, (N_NODES + 127) / 128);

    // layer 1: h = x @ W1
    k_mma_gemm<<<gt1, 256>>>(ahi, alo, w1hi, w1lo, bufA, N_NODES, 512, 256);
    k_proj4<<<N_NODES, 128>>>(bufA, as1, ad1);
    k_agg4<<<N_NODES, 128>>>(bufA, b1, ahi, alo);

    // layer 2
    k_mma_gemm<<<gt1, 256>>>(ahi, alo, w2hi, w2lo, bufA, N_NODES, 512, 512);
    k_proj4<<<N_NODES, 128>>>(bufA, as2, ad2);
    k_agg4<<<N_NODES, 128>>>(bufA, b2, ahi, alo);

    // layer 3
    k_mma_gemm<<<gt3, 256>>>(ahi, alo, w3hi, w3lo, h3, N_NODES, 128, 512);
    k_proj1<<<(N_NODES + 7) / 8, 256>>>(h3, as3, ad3);
    k_agg1<<<(N_NODES + 7) / 8, 256>>>(h3, b3, out);
}

// round 7
// speedup vs baseline: 1.9915x; 1.2110x over previous
#include <cuda_runtime.h>
#include <cuda_bf16.h>
#include <math.h>
#include <stdint.h>

#define N_NODES 30000
#define N_EDGES 480000
#define BUCKET  64

// ---------------- scratch (static device globals; no allocation) ----------------
__device__ float g_bufA[N_NODES * 512];            // GEMM output h (per layer)
__device__ float g_h3[N_NODES * 128];              // layer-3 GEMM output
__device__ __nv_bfloat16 g_ahi[N_NODES * 512];     // GEMM A operand hi
__device__ __nv_bfloat16 g_alo[N_NODES * 512];     // GEMM A operand lo
__device__ __nv_bfloat16 g_w1hi[512 * 256], g_w1lo[512 * 256];   // [N,K]
__device__ __nv_bfloat16 g_w2hi[512 * 512], g_w2lo[512 * 512];
__device__ __nv_bfloat16 g_w3hi[128 * 512], g_w3lo[128 * 512];
__device__ float g_as[N_NODES * 4];
__device__ float g_ad[N_NODES * 4];
__device__ int   g_cnt[N_NODES];
__device__ int   g_csrc[N_NODES * BUCKET];
__device__ int   g_is64;

// ---------------- PTX helpers (base ISA: ldmatrix + mma.sync + cp.async) ----------------
__device__ __forceinline__ uint32_t smem_u32(const void* p) {
    uint32_t a;
    asm("{ .reg .u64 t; cvta.to.shared.u64 t, %1; cvt.u32.u64 %0, t; }" : "=r"(a) : "l"(p));
    return a;
}
__device__ __forceinline__ void ldsm4(uint32_t* r, uint32_t addr) {
    asm volatile("ldmatrix.sync.aligned.m8n8.x4.shared.b16 {%0,%1,%2,%3}, [%4];"
                 : "=r"(r[0]), "=r"(r[1]), "=r"(r[2]), "=r"(r[3]) : "r"(addr));
}
__device__ __forceinline__ void mma16816(float* c, const uint32_t* a, const uint32_t* b) {
    asm volatile(
        "mma.sync.aligned.m16n8k16.row.col.f32.bf16.bf16.f32 "
        "{%0,%1,%2,%3}, {%4,%5,%6,%7}, {%8,%9}, {%0,%1,%2,%3};"
        : "+f"(c[0]), "+f"(c[1]), "+f"(c[2]), "+f"(c[3])
        : "r"(a[0]), "r"(a[1]), "r"(a[2]), "r"(a[3]), "r"(b[0]), "r"(b[1]));
}
__device__ __forceinline__ void cp16(uint32_t dst, const void* src) {
    asm volatile("cp.async.cg.shared.global [%0], [%1], 16;" :: "r"(dst), "l"(src));
}
#define CP_COMMIT() asm volatile("cp.async.commit_group;" ::: "memory")
#define CP_WAIT1()  asm volatile("cp.async.wait_group 1;" ::: "memory")
#define CP_WAIT0()  asm volatile("cp.async.wait_group 0;" ::: "memory")

// ---------------- edge_index dtype probe ----------------
__global__ void k_detect(const void* __restrict__ ei) {
    if (threadIdx.x == 0) {
        const long long* p = (const long long*)ei;
        int ok = 1;
        for (int i = 0; i < 64; i++) {
            long long s = p[i];
            long long d = p[N_EDGES + i];
            if (s < 0 || s >= N_NODES || d < 0 || d >= N_NODES) { ok = 0; break; }
        }
        g_is64 = ok;
    }
}
__device__ __forceinline__ int edge_src(const void* ei, int i) {
    return g_is64 ? (int)((const long long*)ei)[i] : ((const int*)ei)[i];
}
__device__ __forceinline__ int edge_dst(const void* ei, int i) {
    return g_is64 ? (int)((const long long*)ei)[N_EDGES + i] : ((const int*)ei)[N_EDGES + i];
}

// ---------------- bucketed incoming-edge lists ----------------
__global__ void k_initbuckets() {
    int i = blockIdx.x * blockDim.x + threadIdx.x;
    if (i < N_NODES) { g_cnt[i] = 1; g_csrc[i * BUCKET] = i; }
}
__global__ void k_scatter(const void* __restrict__ ei) {
    int i = blockIdx.x * blockDim.x + threadIdx.x;
    if (i < N_EDGES) {
        int s = edge_src(ei, i);
        int d = edge_dst(ei, i);
        int pos = atomicAdd(&g_cnt[d], 1);
        if (pos < BUCKET) g_csrc[d * BUCKET + pos] = s;
    }
}

// zero attention accumulators
__global__ void k_zero_attn() {
    int i = blockIdx.x * blockDim.x + threadIdx.x;
    if (i < N_NODES * 4) { g_as[i] = 0.f; g_ad[i] = 0.f; }
}

// ---------------- float -> bf16 hi/lo splits ----------------
__device__ __forceinline__ void split1(float v, __nv_bfloat16& hi, __nv_bfloat16& lo) {
    hi = __float2bfloat16_rn(v);
    lo = __float2bfloat16_rn(v - __bfloat162float(hi));
}

__global__ void k_splitA(const float* __restrict__ src, __nv_bfloat16* __restrict__ hi,
                         __nv_bfloat16* __restrict__ lo, int n4) {
    int i = blockIdx.x * blockDim.x + threadIdx.x;
    if (i < n4) {
        float4 v = ((const float4*)src)[i];
        __nv_bfloat16 h0, h1, h2, h3, l0, l1, l2, l3;
        split1(v.x, h0, l0); split1(v.y, h1, l1);
        split1(v.z, h2, l2); split1(v.w, h3, l3);
        ((__nv_bfloat162*)hi)[2 * i]     = __nv_bfloat162(h0, h1);
        ((__nv_bfloat162*)hi)[2 * i + 1] = __nv_bfloat162(h2, h3);
        ((__nv_bfloat162*)lo)[2 * i]     = __nv_bfloat162(l0, l1);
        ((__nv_bfloat162*)lo)[2 * i + 1] = __nv_bfloat162(l2, l3);
    }
}

// W [K,N] fp32 -> hi/lo [N,K] bf16 (transpose + split)
__global__ void k_splitW(const float* __restrict__ W, __nv_bfloat16* __restrict__ hi,
                         __nv_bfloat16* __restrict__ lo, int K, int N) {
    int i = blockIdx.x * blockDim.x + threadIdx.x;
    if (i < K * N) {
        int k = i / N, n = i % N;
        __nv_bfloat16 h, l;
        split1(W[i], h, l);
        hi[(size_t)n * K + k] = h;
        lo[(size_t)n * K + k] = l;
    }
}

// ---------------- mma.sync split-bf16 GEMM + fused attention projection ----------------
// C[M,N] fp32 row-major = A[M,K] @ W[K,N]; A*,B* bf16 hi/lo, A in [M,K], B in [N,K].
// CTA 128x128 tile, 256 thr (8 warps 4x2, each 32x64), K chunked by 32.
// cp.async 2-stage pipeline; epilogue also accumulates g_as/g_ad = h . att via atomics.
#define TPAD 40
#define TBYTES (128 * TPAD * 2)      // 10240 per tile
#define STAGE_BYTES (4 * TBYTES)     // 40960 per stage
#define SMEM_TOTAL (2 * STAGE_BYTES) // 81920

__global__ __launch_bounds__(256) void k_mma_gemm(
    const __nv_bfloat16* __restrict__ Ahi, const __nv_bfloat16* __restrict__ Alo,
    const __nv_bfloat16* __restrict__ Bhi, const __nv_bfloat16* __restrict__ Blo,
    float* __restrict__ C,
    const float* __restrict__ att_s, const float* __restrict__ att_d,
    int M, int N, int K, int H)
{
    extern __shared__ char smem[];
    const uint32_t sb = smem_u32(smem);

    int tid = threadIdx.x;
    int lane = tid & 31, wid = tid >> 5;
    int mw = wid & 3, nw = wid >> 2;
    int m0 = blockIdx.y * 128, n0 = blockIdx.x * 128;

    // staging: thread handles rows {tid>>2, tid>>2+64}, 16B chunk cq = tid&3
    int row0 = tid >> 2, cq = tid & 3;
    const uint4* pA[2][2];
    const uint4* pB[2][2];
    bool aok[2];
    uint32_t dstoff[2];
    #pragma unroll
    for (int j = 0; j < 2; j++) {
        int rr = row0 + j * 64;
        int ar = m0 + rr;
        aok[j] = ar < M;
        pA[0][j] = (const uint4*)(Ahi + (size_t)(aok[j] ? ar : 0) * K) + cq;
        pA[1][j] = (const uint4*)(Alo + (size_t)(aok[j] ? ar : 0) * K) + cq;
        pB[0][j] = (const uint4*)(Bhi + (size_t)(n0 + rr) * K) + cq;
        pB[1][j] = (const uint4*)(Blo + (size_t)(n0 + rr) * K) + cq;
        dstoff[j] = (uint32_t)(rr * TPAD + cq * 8) * 2;
    }

    // ldmatrix source offsets (within a stage)
    int arow = mw * 32 + (lane & 15);
    uint32_t aoff = (uint32_t)(arow * TPAD + ((lane >> 4) << 3)) * 2;
    int brow = nw * 64 + (lane & 7) + ((lane >> 4) << 3);
    uint32_t boff = (uint32_t)(brow * TPAD + (((lane >> 3) & 1) << 3)) * 2;

    float acc[2][8][4];
    #pragma unroll
    for (int i = 0; i < 2; i++)
        #pragma unroll
        for (int j = 0; j < 8; j++)
            #pragma unroll
            for (int q = 0; q < 4; q++) acc[i][j][q] = 0.f;

    int nchunk = K >> 5;

    // prologue: stage chunk 0 into buffer 0
    {
        uint32_t base = sb;
        #pragma unroll
        for (int j = 0; j < 2; j++) {
            cp16(base + dstoff[j],              pA[0][j]);
            cp16(base + dstoff[j] + TBYTES,     pA[1][j]);
            cp16(base + dstoff[j] + 2 * TBYTES, pB[0][j]);
            cp16(base + dstoff[j] + 3 * TBYTES, pB[1][j]);
        }
        CP_COMMIT();
    }

    for (int c = 0; c < nchunk; c++) {
        if (c + 1 < nchunk) {
            uint32_t base = sb + ((c + 1) & 1) * STAGE_BYTES;
            int kq = (c + 1) * 4;
            #pragma unroll
            for (int j = 0; j < 2; j++) {
                cp16(base + dstoff[j],              pA[0][j] + kq);
                cp16(base + dstoff[j] + TBYTES,     pA[1][j] + kq);
                cp16(base + dstoff[j] + 2 * TBYTES, pB[0][j] + kq);
                cp16(base + dstoff[j] + 3 * TBYTES, pB[1][j] + kq);
            }
            CP_COMMIT();
            CP_WAIT1();
        } else {
            CP_WAIT0();
        }
        __syncthreads();

        uint32_t st = sb + (c & 1) * STAGE_BYTES;
        uint32_t sAhi = st, sAlo = st + TBYTES, sBhi = st + 2 * TBYTES, sBlo = st + 3 * TBYTES;

        #pragma unroll
        for (int k16 = 0; k16 < 2; k16++) {
            uint32_t kb = k16 * 32;
            uint32_t ahi[2][4], alo[2][4];
            #pragma unroll
            for (int mt = 0; mt < 2; mt++) {
                ldsm4(ahi[mt], sAhi + aoff + mt * (16 * TPAD * 2) + kb);
                ldsm4(alo[mt], sAlo + aoff + mt * (16 * TPAD * 2) + kb);
            }
            uint32_t bhi[8][2], blo[8][2];
            #pragma unroll
            for (int np = 0; np < 4; np++) {
                uint32_t r[4];
                ldsm4(r, sBhi + boff + np * (16 * TPAD * 2) + kb);
                bhi[2 * np][0] = r[0]; bhi[2 * np][1] = r[1];
                bhi[2 * np + 1][0] = r[2]; bhi[2 * np + 1][1] = r[3];
                ldsm4(r, sBlo + boff + np * (16 * TPAD * 2) + kb);
                blo[2 * np][0] = r[0]; blo[2 * np][1] = r[1];
                blo[2 * np + 1][0] = r[2]; blo[2 * np + 1][1] = r[3];
            }
            #pragma unroll
            for (int mt = 0; mt < 2; mt++)
                #pragma unroll
                for (int nt = 0; nt < 8; nt++) {
                    mma16816(acc[mt][nt], ahi[mt], bhi[nt]);
                    mma16816(acc[mt][nt], ahi[mt], blo[nt]);
                    mma16816(acc[mt][nt], alo[mt], bhi[nt]);
                }
        }
        __syncthreads();
    }

    // ---- epilogue: store C + fused attention projection ----
    int rbase = m0 + mw * 32 + (lane >> 2);
    int cbase = n0 + nw * 64 + (lane & 3) * 2;
    int head = (n0 + nw * 64) >> 7;   // 64-col warp slice lies within one head

    float ps[2][2] = {{0.f, 0.f}, {0.f, 0.f}};   // [mt][r / r+8] partial h.att_src
    float pd[2][2] = {{0.f, 0.f}, {0.f, 0.f}};

    #pragma unroll
    for (int mt = 0; mt < 2; mt++) {
        int r = rbase + mt * 16;
        #pragma unroll
        for (int nt = 0; nt < 8; nt++) {
            int col = cbase + nt * 8;
            float s0 = __ldg(att_s + col), s1 = __ldg(att_s + col + 1);
            float d0 = __ldg(att_d + col), d1 = __ldg(att_d + col + 1);
            ps[mt][0] += s0 * acc[mt][nt][0] + s1 * acc[mt][nt][1];
            pd[mt][0] += d0 * acc[mt][nt][0] + d1 * acc[mt][nt][1];
            ps[mt][1] += s0 * acc[mt][nt][2] + s1 * acc[mt][nt][3];
            pd[mt][1] += d0 * acc[mt][nt][2] + d1 * acc[mt][nt][3];
            if (r < M)
                *(float2*)(C + (size_t)r * N + col) = make_float2(acc[mt][nt][0], acc[mt][nt][1]);
            if (r + 8 < M)
                *(float2*)(C + (size_t)(r + 8) * N + col) = make_float2(acc[mt][nt][2], acc[mt][nt][3]);
        }
    }
    // quad reduction (lanes sharing a row differ only in lane&3)
    #pragma unroll
    for (int mt = 0; mt < 2; mt++)
        #pragma unroll
        for (int hh = 0; hh < 2; hh++) {
            float vs = ps[mt][hh], vd = pd[mt][hh];
            vs += __shfl_xor_sync(0xffffffffu, vs, 1);
            vs += __shfl_xor_sync(0xffffffffu, vs, 2);
            vd += __shfl_xor_sync(0xffffffffu, vd, 1);
            vd += __shfl_xor_sync(0xffffffffu, vd, 2);
            if ((lane & 3) == 0) {
                int r = rbase + mt * 16 + hh * 8;
                if (r < M) {
                    atomicAdd(&g_as[r * H + head], vs);
                    atomicAdd(&g_ad[r * H + head], vd);
                }
            }
        }
}

__device__ __forceinline__ float lrelu(float a) { return a > 0.f ? a : 0.2f * a; }

// ---------------- fused softmax + aggregation -> bf16 hi/lo for next GEMM ----------------
__global__ void k_agg4(const float* __restrict__ h, const float* __restrict__ bias,
                       __nv_bfloat16* __restrict__ ohi, __nv_bfloat16* __restrict__ olo)
{
    int n = blockIdx.x;
    int w = threadIdx.x >> 5, lane = threadIdx.x & 31;
    int beg = n * BUCKET;
    int cnt = min(g_cnt[n], BUCKET);
    int end = beg + cnt;
    float adst = g_ad[n * 4 + w];

    float mx = -1e30f;
    for (int i = beg + lane; i < end; i += 32)
        mx = fmaxf(mx, g_as[g_csrc[i] * 4 + w]);
    #pragma unroll
    for (int d = 16; d; d >>= 1)
        mx = fmaxf(mx, __shfl_xor_sync(0xffffffffu, mx, d));
    float m = lrelu(mx + adst);

    float4 acc = make_float4(0.f, 0.f, 0.f, 0.f);
    float denom = 0.f;
    int c0 = w * 128 + lane * 4;
    #pragma unroll 2
    for (int i = beg; i < end; i++) {
        int s = g_csrc[i];
        float a = lrelu(g_as[s * 4 + w] + adst);
        float ex = __expf(a - m);
        denom += ex;
        float4 hv = *(const float4*)(h + (size_t)s * 512 + c0);
        acc.x = fmaf(ex, hv.x, acc.x);
        acc.y = fmaf(ex, hv.y, acc.y);
        acc.z = fmaf(ex, hv.z, acc.z);
        acc.w = fmaf(ex, hv.w, acc.w);
    }
    float inv = 1.f / denom;
    float4 b = *(const float4*)(bias + c0);
    float o0 = fmaxf(acc.x * inv + b.x, 0.f);
    float o1 = fmaxf(acc.y * inv + b.y, 0.f);
    float o2 = fmaxf(acc.z * inv + b.z, 0.f);
    float o3 = fmaxf(acc.w * inv + b.w, 0.f);
    __nv_bfloat16 h0, h1, h2, h3, l0, l1, l2, l3;
    split1(o0, h0, l0); split1(o1, h1, l1); split1(o2, h2, l2); split1(o3, h3, l3);
    size_t idx = (size_t)n * 512 + c0;
    *(__nv_bfloat162*)(ohi + idx)     = __nv_bfloat162(h0, h1);
    *(__nv_bfloat162*)(ohi + idx + 2) = __nv_bfloat162(h2, h3);
    *(__nv_bfloat162*)(olo + idx)     = __nv_bfloat162(l0, l1);
    *(__nv_bfloat162*)(olo + idx + 2) = __nv_bfloat162(l2, l3);
}

__global__ void k_agg1(const float* __restrict__ h, const float* __restrict__ bias,
                       float* __restrict__ out)
{
    int node = blockIdx.x * 8 + (threadIdx.x >> 5);
    if (node >= N_NODES) return;
    int lane = threadIdx.x & 31;
    int beg = node * BUCKET;
    int cnt = min(g_cnt[node], BUCKET);
    int end = beg + cnt;
    float adst = g_ad[node];

    float mx = -1e30f;
    for (int i = beg + lane; i < end; i += 32)
        mx = fmaxf(mx, g_as[g_csrc[i]]);
    #pragma unroll
    for (int d = 16; d; d >>= 1)
        mx = fmaxf(mx, __shfl_xor_sync(0xffffffffu, mx, d));
    float m = lrelu(mx + adst);

    float4 acc = make_float4(0.f, 0.f, 0.f, 0.f);
    float denom = 0.f;
    int c0 = lane * 4;
    #pragma unroll 2
    for (int i = beg; i < end; i++) {
        int s = g_csrc[i];
        float a = lrelu(g_as[s] + adst);
        float ex = __expf(a - m);
        denom += ex;
        float4 hv = *(const float4*)(h + (size_t)s * 128 + c0);
        acc.x = fmaf(ex, hv.x, acc.x);
        acc.y = fmaf(ex, hv.y, acc.y);
        acc.z = fmaf(ex, hv.z, acc.z);
        acc.w = fmaf(ex, hv.w, acc.w);
    }
    float inv = 1.f / denom;
    float4 b = *(const float4*)(bias + c0);
    float4 o;
    o.x = acc.x * inv + b.x;
    o.y = acc.y * inv + b.y;
    o.z = acc.z * inv + b.z;
    o.w = acc.w * inv + b.w;
    *(float4*)(out + (size_t)node * 128 + c0) = o;
}

// ---------------- launch ----------------
extern "C" void kernel_launch(void* const* d_in, const int* in_sizes, int n_in,
                              void* d_out, int out_size)
{
    const float* x    = (const float*)d_in[0];
    const void*  ei   = d_in[1];
    const float* W1   = (const float*)d_in[2];
    const float* as1  = (const float*)d_in[3];
    const float* ad1  = (const float*)d_in[4];
    const float* b1   = (const float*)d_in[5];
    const float* W2   = (const float*)d_in[6];
    const float* as2  = (const float*)d_in[7];
    const float* ad2  = (const float*)d_in[8];
    const float* b2   = (const float*)d_in[9];
    const float* W3   = (const float*)d_in[10];
    const float* as3  = (const float*)d_in[11];
    const float* ad3  = (const float*)d_in[12];
    const float* b3   = (const float*)d_in[13];
    float*       out  = (float*)d_out;

    float *bufA, *h3;
    __nv_bfloat16 *ahi, *alo, *w1hi, *w1lo, *w2hi, *w2lo, *w3hi, *w3lo;
    cudaGetSymbolAddress((void**)&bufA, g_bufA);
    cudaGetSymbolAddress((void**)&h3,   g_h3);
    cudaGetSymbolAddress((void**)&ahi,  g_ahi);
    cudaGetSymbolAddress((void**)&alo,  g_alo);
    cudaGetSymbolAddress((void**)&w1hi, g_w1hi);
    cudaGetSymbolAddress((void**)&w1lo, g_w1lo);
    cudaGetSymbolAddress((void**)&w2hi, g_w2hi);
    cudaGetSymbolAddress((void**)&w2lo, g_w2lo);
    cudaGetSymbolAddress((void**)&w3hi, g_w3hi);
    cudaGetSymbolAddress((void**)&w3lo, g_w3lo);

    cudaFuncSetAttribute(k_mma_gemm, cudaFuncAttributeMaxDynamicSharedMemorySize, SMEM_TOTAL);

    // graph build + operand prep
    k_detect<<<1, 32>>>(ei);
    k_initbuckets<<<(N_NODES + 255) / 256, 256>>>();
    k_scatter<<<(N_EDGES + 255) / 256, 256>>>(ei);
    k_splitW<<<(256 * 512 + 255) / 256, 256>>>(W1, w1hi, w1lo, 256, 512);
    k_splitW<<<(512 * 512 + 255) / 256, 256>>>(W2, w2hi, w2lo, 512, 512);
    k_splitW<<<(512 * 128 + 255) / 256, 256>>>(W3, w3hi, w3lo, 512, 128);
    k_splitA<<<(N_NODES * 256 / 4 + 255) / 256, 256>>>(x, ahi, alo, N_NODES * 256 / 4);

    dim3 gt1(512 / 128, (N_NODES + 127) / 128);
    dim3 gt3(128 / 128, (N_NODES + 127) / 128);
    int zgrid = (N_NODES * 4 + 255) / 256;

    // layer 1
    k_zero_attn<<<zgrid, 256>>>();
    k_mma_gemm<<<gt1, 256, SMEM_TOTAL>>>(ahi, alo, w1hi, w1lo, bufA, as1, ad1,
                                         N_NODES, 512, 256, 4);
    k_agg4<<<N_NODES, 128>>>(bufA, b1, ahi, alo);

    // layer 2
    k_zero_attn<<<zgrid, 256>>>();
    k_mma_gemm<<<gt1, 256, SMEM_TOTAL>>>(ahi, alo, w2hi, w2lo, bufA, as2, ad2,
                                         N_NODES, 512, 512, 4);
    k_agg4<<<N_NODES, 128>>>(bufA, b2, ahi, alo);

    // layer 3
    k_zero_attn<<<zgrid, 256>>>();
    k_mma_gemm<<<gt3, 256, SMEM_TOTAL>>>(ahi, alo, w3hi, w3lo, h3, as3, ad3,
                                         N_NODES, 128, 512, 1);
    k_agg1<<<(N_NODES + 7) / 8, 256>>>(h3, b3, out);
}